// round 1
// baseline (speedup 1.0000x reference)
#include <cuda_runtime.h>
#include <math.h>

#define NPTS 20000
#define KNN  16
#define C    256
#define G    16
#define EPS  1e-5f
#define P    8          // points per block in K2
#define K1_ROWS 32      // feat rows per block in K1

// ---------------- scratch (static device memory; no allocations) ----------
__device__ float g_vall[NPTS * C];     // v_all = feat@Wv + bv
__device__ float g_qW[NPTS * G];       // relu(bn(feat@Wq+bq)) @ Ww1
__device__ float g_kW[NPTS * G];       // relu(bn(feat@Wk+bk)) @ Ww1
__device__ float g_At[G * C];          // (Wp2 @ Ww1)^T, layout [g][k]
__device__ float g_sq[C], g_tq[C];     // folded BN+bias for q
__device__ float g_sk[C], g_tk[C];     // folded BN+bias for k
__device__ float g_sp[C], g_tp[C];     // folded BN+bias for pos MLP layer 1
__device__ float g_sw[G], g_cw[G];     // folded BN for weight MLP (incl. bw1 + bp2@Ww1)

// ---------------- prep: fold BN params --------------------------------------
// bn param layout: (4,C) stacked [gamma, beta, mean, var]
__global__ void prep_fold(const float* __restrict__ bq, const float* __restrict__ bnq,
                          const float* __restrict__ bk, const float* __restrict__ bnk,
                          const float* __restrict__ bp1, const float* __restrict__ bnp,
                          const float* __restrict__ bw1, const float* __restrict__ bnw,
                          const float* __restrict__ bp2, const float* __restrict__ ww1) {
    int t = threadIdx.x;
    if (t < C) {
        float s;
        s = bnq[t] * rsqrtf(bnq[3 * C + t] + EPS);
        g_sq[t] = s; g_tq[t] = (bq[t] - bnq[2 * C + t]) * s + bnq[C + t];
        s = bnk[t] * rsqrtf(bnk[3 * C + t] + EPS);
        g_sk[t] = s; g_tk[t] = (bk[t] - bnk[2 * C + t]) * s + bnk[C + t];
        s = bnp[t] * rsqrtf(bnp[3 * C + t] + EPS);
        g_sp[t] = s; g_tp[t] = (bp1[t] - bnp[2 * C + t]) * s + bnp[C + t];
    }
    if (t < G) {
        float s = bnw[t] * rsqrtf(bnw[3 * G + t] + EPS);
        float bp2w = 0.f;
        for (int c = 0; c < C; c++) bp2w += bp2[c] * ww1[c * G + t];
        g_sw[t] = s;
        g_cw[t] = (bw1[t] + bp2w - bnw[2 * G + t]) * s + bnw[G + t];
    }
}

// A^T[g][kk] = sum_c Wp2[kk][c] * Ww1[c][g]
__global__ void prep_At(const float* __restrict__ wp2, const float* __restrict__ ww1) {
    int kk = blockIdx.x * 16 + (threadIdx.x >> 4);
    int g  = threadIdx.x & 15;
    float s = 0.f;
    #pragma unroll 4
    for (int c = 0; c < C; c++) s = fmaf(wp2[kk * C + c], ww1[c * G + g], s);
    g_At[g * C + kk] = s;
}

// ---------------- K1: fused q/k/v GEMM + Ww1 projections ------------------
__global__ __launch_bounds__(256) void k1_qkv(
    const float* __restrict__ feat,
    const float* __restrict__ wq, const float* __restrict__ wk,
    const float* __restrict__ wv, const float* __restrict__ bv,
    const float* __restrict__ ww1) {
    extern __shared__ float sm[];
    float* feat_s = sm;                    // 32*256
    float* ybuf   = sm + K1_ROWS * C;      // 32*256 (q then k activations)
    float* ww1_s  = sm + 2 * K1_ROWS * C;  // 256*16

    int t  = threadIdx.x;
    int r0 = blockIdx.x * K1_ROWS;

    for (int i = t; i < K1_ROWS * C; i += 256) feat_s[i] = feat[r0 * C + i];
    for (int i = t; i < C * G; i += 256) ww1_s[i] = ww1[i];
    __syncthreads();

    for (int pass = 0; pass < 3; pass++) {
        const float* W = (pass == 0) ? wq : ((pass == 1) ? wk : wv);
        float acc[K1_ROWS];
        #pragma unroll
        for (int r = 0; r < K1_ROWS; r++) acc[r] = 0.f;

        for (int k = 0; k < C; k += 4) {
            float w0 = W[(k + 0) * C + t];
            float w1 = W[(k + 1) * C + t];
            float w2 = W[(k + 2) * C + t];
            float w3 = W[(k + 3) * C + t];
            #pragma unroll
            for (int r = 0; r < K1_ROWS; r++) {
                float4 f = *(const float4*)&feat_s[r * C + k];
                acc[r] = fmaf(f.x, w0, acc[r]);
                acc[r] = fmaf(f.y, w1, acc[r]);
                acc[r] = fmaf(f.z, w2, acc[r]);
                acc[r] = fmaf(f.w, w3, acc[r]);
            }
        }

        if (pass == 2) {
            float bvc = bv[t];
            #pragma unroll
            for (int r = 0; r < K1_ROWS; r++)
                g_vall[(r0 + r) * C + t] = acc[r] + bvc;
        } else {
            float sc = (pass == 0) ? g_sq[t] : g_sk[t];
            float sh = (pass == 0) ? g_tq[t] : g_tk[t];
            #pragma unroll
            for (int r = 0; r < K1_ROWS; r++)
                ybuf[r * C + t] = fmaxf(fmaf(acc[r], sc, sh), 0.f);
            __syncthreads();
            float* dst = (pass == 0) ? g_qW : g_kW;
            for (int o = t; o < K1_ROWS * G; o += 256) {
                int r = o >> 4, g = o & 15;
                float s = 0.f;
                for (int k = 0; k < C; k += 4) {
                    float4 y = *(const float4*)&ybuf[r * C + k];
                    s = fmaf(y.x, ww1_s[(k + 0) * G + g], s);
                    s = fmaf(y.y, ww1_s[(k + 1) * G + g], s);
                    s = fmaf(y.z, ww1_s[(k + 2) * G + g], s);
                    s = fmaf(y.w, ww1_s[(k + 3) * G + g], s);
                }
                dst[(r0 + r) * G + g] = s;
            }
            __syncthreads();  // ybuf reused next pass
        }
    }
}

// ---------------- K2: fused per-point grouped attention -------------------
struct K2Smem {
    float hid[P * 16 * C];    // hidden[p][s][c]; becomes hw[p][g][c] in place
    float At_s[G * C];        // A^T staged
    float buf1[P * 16 * G];   // lb -> u
    float buf2[P * 16 * G];   // logit2 -> softmax weights w
    float pos_s[P * 16 * 4];
    float wsum[P * G];
    float mask_s[P * 16];
    int   idx_s[P * 16];
    float ww2_s[G * G];
    float bw2_s[G];
    float bp2_s[C];
    float sw_s[G], cw_s[G];
};

__global__ __launch_bounds__(512) void k2_attn(
    const float* __restrict__ coord, const int* __restrict__ knn,
    const float* __restrict__ wp1,   const float* __restrict__ wp2,
    const float* __restrict__ bp2,   const float* __restrict__ ww2,
    const float* __restrict__ bw2,   float* __restrict__ out) {
    extern __shared__ char smraw[];
    K2Smem& S = *reinterpret_cast<K2Smem*>(smraw);
    int t  = threadIdx.x;
    int n0 = blockIdx.x * P;

    for (int i = t; i < G * C; i += 512) S.At_s[i] = g_At[i];
    for (int i = t; i < G * G; i += 512) S.ww2_s[i] = ww2[i];
    for (int i = t; i < C; i += 512)     S.bp2_s[i] = bp2[i];
    if (t < G) { S.bw2_s[t] = bw2[t]; S.sw_s[t] = g_sw[t]; S.cw_s[t] = g_cw[t]; }

    // phase 1a: gather indices / mask / relative positions
    if (t < P * 16) {
        int p = t >> 4, s = t & 15, n = n0 + p;
        int id  = knn[n * KNN + s];
        int ip1 = id + 1;
        float m = (float)((ip1 > 0) - (ip1 < 0));   // sign(idx+1)
        int sid = (id > 0) ? id : 0;                // clip(idx,0)
        S.idx_s[t]  = sid;
        S.mask_s[t] = m;
        #pragma unroll
        for (int d = 0; d < 3; d++)
            S.pos_s[t * 4 + d] = (coord[sid * 3 + d] - coord[n * 3 + d]) * m;
        (void)s;
    }
    __syncthreads();

    // phase 1b: logit base lb = mask*kW[idx] - qW[n]
    for (int o = t; o < P * 16 * G; o += 512) {
        int p = o >> 8, ps = o >> 4, g = o & 15;
        S.buf1[o] = S.mask_s[ps] * g_kW[S.idx_s[ps] * G + g] - g_qW[(n0 + p) * G + g];
    }

    // phase 2: hidden = relu(bn(pos @ Wp1 + bp1))
    {
        int c = t & 255;
        float w0 = wp1[c], w1 = wp1[C + c], w2 = wp1[2 * C + c];
        float sc = g_sp[c], sh = g_tp[c];
        for (int ps = t >> 8; ps < P * 16; ps += 2) {
            float px = S.pos_s[ps * 4 + 0];
            float py = S.pos_s[ps * 4 + 1];
            float pz = S.pos_s[ps * 4 + 2];
            float h = fmaf(px, w0, fmaf(py, w1, pz * w2));
            S.hid[ps * C + c] = fmaxf(fmaf(h, sc, sh), 0.f);
        }
    }
    __syncthreads();

    // phase 3: u = relu(sw*(hidden@A + lb) + cw)
    for (int o = t; o < P * 16 * G; o += 512) {
        int ps = o >> 4, g = o & 15;
        const float4* hr = (const float4*)&S.hid[ps * C];
        const float4* ar = (const float4*)&S.At_s[g * C];
        float acc = 0.f;
        #pragma unroll
        for (int kk = 0; kk < C / 4; kk++) {
            float4 h = hr[kk], a = ar[kk];
            acc = fmaf(h.x, a.x, acc); acc = fmaf(h.y, a.y, acc);
            acc = fmaf(h.z, a.z, acc); acc = fmaf(h.w, a.w, acc);
        }
        float u = fmaf(acc + S.buf1[o], S.sw_s[g], S.cw_s[g]);
        S.buf1[o] = fmaxf(u, 0.f);
    }
    __syncthreads();

    // phase 3b: logit2 = u @ Ww2 + bw2
    for (int o = t; o < P * 16 * G; o += 512) {
        int ps = o >> 4, g2 = o & 15;
        float acc = S.bw2_s[g2];
        #pragma unroll
        for (int g = 0; g < G; g++)
            acc = fmaf(S.buf1[ps * G + g], S.ww2_s[g * G + g2], acc);
        S.buf2[o] = acc;
    }
    __syncthreads();

    // phase 4a: softmax over neighbors s, per (p,g); apply mask
    if (t < P * G) {
        int p = t >> 4, g = t & 15;
        float mx = -1e30f;
        #pragma unroll
        for (int s = 0; s < 16; s++) mx = fmaxf(mx, S.buf2[(p * 16 + s) * G + g]);
        float e[16], sum = 0.f;
        #pragma unroll
        for (int s = 0; s < 16; s++) {
            e[s] = __expf(S.buf2[(p * 16 + s) * G + g] - mx);
            sum += e[s];
        }
        float inv = 1.f / sum;
        float ws = 0.f;
        #pragma unroll
        for (int s = 0; s < 16; s++) {
            float w = e[s] * inv * S.mask_s[p * 16 + s];
            S.buf2[(p * 16 + s) * G + g] = w;
            ws += w;
        }
        S.wsum[t] = ws;
    }
    __syncthreads();

    // phase 4b: hw[p][g][:] = sum_s w[p][s][g] * hidden[p][s][:]   (in place)
    {
        int p = t >> 6, k0 = (t & 63) * 4;
        #pragma unroll
        for (int rep = 0; rep < 2; rep++) {
            int kc = k0 + rep * 2;
            float2 acc[16];
            #pragma unroll
            for (int g = 0; g < 16; g++) acc[g] = make_float2(0.f, 0.f);
            #pragma unroll
            for (int s = 0; s < 16; s++) {
                float2 h = *(const float2*)&S.hid[(p * 16 + s) * C + kc];
                const float4* wr = (const float4*)&S.buf2[(p * 16 + s) * G];
                #pragma unroll
                for (int gq = 0; gq < 4; gq++) {
                    float4 wv = wr[gq];
                    acc[gq*4+0].x = fmaf(wv.x, h.x, acc[gq*4+0].x);
                    acc[gq*4+0].y = fmaf(wv.x, h.y, acc[gq*4+0].y);
                    acc[gq*4+1].x = fmaf(wv.y, h.x, acc[gq*4+1].x);
                    acc[gq*4+1].y = fmaf(wv.y, h.y, acc[gq*4+1].y);
                    acc[gq*4+2].x = fmaf(wv.z, h.x, acc[gq*4+2].x);
                    acc[gq*4+2].y = fmaf(wv.z, h.y, acc[gq*4+2].y);
                    acc[gq*4+3].x = fmaf(wv.w, h.x, acc[gq*4+3].x);
                    acc[gq*4+3].y = fmaf(wv.w, h.y, acc[gq*4+3].y);
                }
            }
            #pragma unroll
            for (int g = 0; g < 16; g++)
                *(float2*)&S.hid[(p * 16 + g) * C + kc] = acc[g];
        }
    }
    __syncthreads();

    // phase 5: out[c] = sum_s w*v[idx][c] + hw[g]·Wp2[:,c] + bp2[c]*wsum
    {
        int c = t & 255, ph = t >> 8, g = c >> 4;
        float acc[4] = {0.f, 0.f, 0.f, 0.f};
        #pragma unroll
        for (int s = 0; s < 16; s++) {
            #pragma unroll
            for (int pp = 0; pp < 4; pp++) {
                int ps = (ph * 4 + pp) * 16 + s;
                acc[pp] = fmaf(S.buf2[ps * G + g], g_vall[S.idx_s[ps] * C + c], acc[pp]);
            }
        }
        for (int k = 0; k < C; k += 4) {
            float wpa = wp2[(k + 0) * C + c];
            float wpb = wp2[(k + 1) * C + c];
            float wpc = wp2[(k + 2) * C + c];
            float wpd = wp2[(k + 3) * C + c];
            #pragma unroll
            for (int pp = 0; pp < 4; pp++) {
                const float4 hh = *(const float4*)&S.hid[((ph * 4 + pp) * 16 + g) * C + k];
                acc[pp] = fmaf(hh.x, wpa, acc[pp]);
                acc[pp] = fmaf(hh.y, wpb, acc[pp]);
                acc[pp] = fmaf(hh.z, wpc, acc[pp]);
                acc[pp] = fmaf(hh.w, wpd, acc[pp]);
            }
        }
        float b = S.bp2_s[c];
        #pragma unroll
        for (int pp = 0; pp < 4; pp++) {
            int p = ph * 4 + pp;
            out[(n0 + p) * C + c] = acc[pp] + b * S.wsum[p * G + g];
        }
    }
}

// ---------------- launch ----------------------------------------------------
extern "C" void kernel_launch(void* const* d_in, const int* in_sizes, int n_in,
                              void* d_out, int out_size) {
    (void)in_sizes; (void)n_in; (void)out_size;
    const float* feat  = (const float*)d_in[0];
    const float* coord = (const float*)d_in[1];
    const int*   knn   = (const int*)  d_in[2];
    const float* Wq = (const float*)d_in[3];  const float* bq = (const float*)d_in[4];  const float* bnq = (const float*)d_in[5];
    const float* Wk = (const float*)d_in[6];  const float* bk = (const float*)d_in[7];  const float* bnk = (const float*)d_in[8];
    const float* Wv = (const float*)d_in[9];  const float* bv = (const float*)d_in[10];
    const float* Wp1 = (const float*)d_in[11]; const float* bp1 = (const float*)d_in[12]; const float* bnp = (const float*)d_in[13];
    const float* Wp2 = (const float*)d_in[14]; const float* bp2 = (const float*)d_in[15];
    const float* Ww1 = (const float*)d_in[16]; const float* bw1 = (const float*)d_in[17]; const float* bnw = (const float*)d_in[18];
    const float* Ww2 = (const float*)d_in[19]; const float* bw2 = (const float*)d_in[20];
    float* out = (float*)d_out;

    cudaFuncSetAttribute(k1_qkv,  cudaFuncAttributeMaxDynamicSharedMemorySize, 81920);
    cudaFuncSetAttribute(k2_attn, cudaFuncAttributeMaxDynamicSharedMemorySize, (int)sizeof(K2Smem));

    prep_fold<<<1, 256>>>(bq, bnq, bk, bnk, bp1, bnp, bw1, bnw, bp2, Ww1);
    prep_At<<<16, 256>>>(Wp2, Ww1);
    k1_qkv<<<NPTS / K1_ROWS, 256, 81920>>>(feat, Wq, Wk, Wv, bv, Ww1);
    k2_attn<<<NPTS / P, 512, sizeof(K2Smem)>>>(coord, knn, Wp1, Wp2, bp2, Ww2, bw2, out);
}

// round 2
// speedup vs baseline: 2.2463x; 2.2463x over previous
#include <cuda_runtime.h>
#include <math.h>

#define NPTS 20000
#define KNN  16
#define C    256
#define G    16
#define EPS  1e-5f
#define P    4          // points per block in K2
#define BM   32         // feat rows per block in K1
#define CP   260        // padded row stride for hid (multiple of 4, !=0 mod 32)

// ---------------- scratch (static device memory; no allocations) ----------
__device__ float g_vall[NPTS * C];     // v_all = feat@Wv + bv
__device__ float g_qW[NPTS * G];       // relu(bn(feat@Wq+bq)) @ Ww1
__device__ float g_kW[NPTS * G];       // relu(bn(feat@Wk+bk)) @ Ww1
__device__ float g_A4[G * C];          // (Wp2 @ Ww1), k-interleaved: [kb][g][4k]
__device__ float g_wp2t[C * C];        // Wp2^T: [c][k]
__device__ float g_sq[C], g_tq[C];     // folded BN+bias for q
__device__ float g_sk[C], g_tk[C];     // folded BN+bias for k
__device__ float g_sp[C], g_tp[C];     // folded BN+bias for pos MLP layer 1
__device__ float g_sw[G], g_cw[G];     // folded BN for weight MLP (incl. bw1 + bp2@Ww1)

// ---------------- prep kernels ---------------------------------------------
__global__ void prep_fold(const float* __restrict__ bq, const float* __restrict__ bnq,
                          const float* __restrict__ bk, const float* __restrict__ bnk,
                          const float* __restrict__ bp1, const float* __restrict__ bnp,
                          const float* __restrict__ bw1, const float* __restrict__ bnw,
                          const float* __restrict__ bp2, const float* __restrict__ ww1) {
    int t = threadIdx.x;
    if (t < C) {
        float s;
        s = bnq[t] * rsqrtf(bnq[3 * C + t] + EPS);
        g_sq[t] = s; g_tq[t] = (bq[t] - bnq[2 * C + t]) * s + bnq[C + t];
        s = bnk[t] * rsqrtf(bnk[3 * C + t] + EPS);
        g_sk[t] = s; g_tk[t] = (bk[t] - bnk[2 * C + t]) * s + bnk[C + t];
        s = bnp[t] * rsqrtf(bnp[3 * C + t] + EPS);
        g_sp[t] = s; g_tp[t] = (bp1[t] - bnp[2 * C + t]) * s + bnp[C + t];
    }
    if (t < G) {
        float s = bnw[t] * rsqrtf(bnw[3 * G + t] + EPS);
        float bp2w = 0.f;
        for (int c = 0; c < C; c++) bp2w += bp2[c] * ww1[c * G + t];
        g_sw[t] = s;
        g_cw[t] = (bw1[t] + bp2w - bnw[2 * G + t]) * s + bnw[G + t];
    }
}

// A[g][kk] = sum_c Wp2[kk][c] * Ww1[c][g], stored k-interleaved for ph3
__global__ void prep_At(const float* __restrict__ wp2, const float* __restrict__ ww1) {
    int kk = blockIdx.x * 16 + (threadIdx.x >> 4);
    int g  = threadIdx.x & 15;
    float s = 0.f;
    #pragma unroll 4
    for (int c = 0; c < C; c++) s = fmaf(wp2[kk * C + c], ww1[c * G + g], s);
    g_A4[((kk >> 2) * G + g) * 4 + (kk & 3)] = s;
}

__global__ void prep_wp2t(const float* __restrict__ wp2) {
    int k = blockIdx.x, c = threadIdx.x;
    g_wp2t[c * C + k] = wp2[k * C + c];
}

// ---------------- K1: fused q/k/v GEMM + Ww1 projections ------------------
// 256 threads: 128 col-threads (2 cols each) x 2 row-groups (16 rows each)
__global__ __launch_bounds__(256, 2) void k1_qkv(
    const float* __restrict__ feat,
    const float* __restrict__ wq, const float* __restrict__ wk,
    const float* __restrict__ wv, const float* __restrict__ bv,
    const float* __restrict__ ww1) {
    extern __shared__ float sm[];
    float* feat_s = sm;                 // 32*256
    float* ybuf   = sm + BM * C;        // 32*256
    float* ww1_s  = sm + 2 * BM * C;    // 256*16

    int t   = threadIdx.x;
    int r0b = blockIdx.x * BM;

    for (int i = t; i < BM * C / 4; i += 256)
        *(float4*)&feat_s[i * 4] = *(const float4*)&feat[r0b * C + i * 4];
    for (int i = t; i < C * G / 4; i += 256)
        *(float4*)&ww1_s[i * 4] = *(const float4*)&ww1[i * 4];
    __syncthreads();

    int ct = t & 127, c0 = ct * 2;
    int rg = t >> 7,  r0 = rg * 16;

    #pragma unroll 1
    for (int pass = 0; pass < 3; pass++) {
        const float* W = (pass == 0) ? wq : ((pass == 1) ? wk : wv);
        float acc[16][2];
        #pragma unroll
        for (int r = 0; r < 16; r++) { acc[r][0] = 0.f; acc[r][1] = 0.f; }

        #pragma unroll 2
        for (int k = 0; k < C; k += 4) {
            float2 w0 = *(const float2*)&W[(k + 0) * C + c0];
            float2 w1 = *(const float2*)&W[(k + 1) * C + c0];
            float2 w2 = *(const float2*)&W[(k + 2) * C + c0];
            float2 w3 = *(const float2*)&W[(k + 3) * C + c0];
            #pragma unroll
            for (int r = 0; r < 16; r++) {
                float4 f = *(const float4*)&feat_s[(r0 + r) * C + k];
                acc[r][0] = fmaf(f.x, w0.x, acc[r][0]); acc[r][1] = fmaf(f.x, w0.y, acc[r][1]);
                acc[r][0] = fmaf(f.y, w1.x, acc[r][0]); acc[r][1] = fmaf(f.y, w1.y, acc[r][1]);
                acc[r][0] = fmaf(f.z, w2.x, acc[r][0]); acc[r][1] = fmaf(f.z, w2.y, acc[r][1]);
                acc[r][0] = fmaf(f.w, w3.x, acc[r][0]); acc[r][1] = fmaf(f.w, w3.y, acc[r][1]);
            }
        }

        if (pass == 2) {
            float b0 = bv[c0], b1 = bv[c0 + 1];
            #pragma unroll
            for (int r = 0; r < 16; r++) {
                float2 o; o.x = acc[r][0] + b0; o.y = acc[r][1] + b1;
                *(float2*)&g_vall[(r0b + r0 + r) * C + c0] = o;
            }
        } else {
            float s0, h0, s1, h1;
            if (pass == 0) { s0 = g_sq[c0]; h0 = g_tq[c0]; s1 = g_sq[c0+1]; h1 = g_tq[c0+1]; }
            else           { s0 = g_sk[c0]; h0 = g_tk[c0]; s1 = g_sk[c0+1]; h1 = g_tk[c0+1]; }
            #pragma unroll
            for (int r = 0; r < 16; r++) {
                float2 y;
                y.x = fmaxf(fmaf(acc[r][0], s0, h0), 0.f);
                y.y = fmaxf(fmaf(acc[r][1], s1, h1), 0.f);
                *(float2*)&ybuf[(r0 + r) * C + c0] = y;
            }
            __syncthreads();
            // projection: thread handles rows (rr, rr+16) for one g
            int g_ = t & 15, rr = t >> 4;
            float p0 = 0.f, p1 = 0.f;
            #pragma unroll 4
            for (int k = 0; k < C; k += 4) {
                float4 ya = *(const float4*)&ybuf[rr * C + k];
                float4 yb = *(const float4*)&ybuf[(rr + 16) * C + k];
                float q0 = ww1_s[(k + 0) * G + g_];
                float q1 = ww1_s[(k + 1) * G + g_];
                float q2 = ww1_s[(k + 2) * G + g_];
                float q3 = ww1_s[(k + 3) * G + g_];
                p0 = fmaf(ya.x, q0, p0); p1 = fmaf(yb.x, q0, p1);
                p0 = fmaf(ya.y, q1, p0); p1 = fmaf(yb.y, q1, p1);
                p0 = fmaf(ya.z, q2, p0); p1 = fmaf(yb.z, q2, p1);
                p0 = fmaf(ya.w, q3, p0); p1 = fmaf(yb.w, q3, p1);
            }
            float* dst = (pass == 0) ? g_qW : g_kW;
            dst[(r0b + rr) * G + g_]      = p0;
            dst[(r0b + rr + 16) * G + g_] = p1;
            __syncthreads();   // ybuf reused next pass
        }
    }
}

// ---------------- K2: fused per-point grouped attention -------------------
struct K2S {
    float hid[P * 16 * CP];   // 64 x 260 = 66560 B; becomes hw in place
    float A4s[4096];          // 16 KB, k-interleaved A
    float buf1[P * 16 * G];   // lb -> u
    float buf2[P * 16 * G];   // logit2 -> weights
    float pos[P * 16 * 4];
    float wsum[P * G];
    float mask[P * 16];
    int   idx[P * 16];
    float ww2[G * G];
    float bp2s[C];
    float sw[G], cw[G], bw2s[G];
};

__global__ __launch_bounds__(256, 2) void k2_attn(
    const float* __restrict__ coord, const int* __restrict__ knn,
    const float* __restrict__ wp1,   const float* __restrict__ bp2,
    const float* __restrict__ ww2,   const float* __restrict__ bw2,
    float* __restrict__ out) {
    extern __shared__ char smraw[];
    K2S& S = *reinterpret_cast<K2S*>(smraw);
    int t  = threadIdx.x;
    int n0 = blockIdx.x * P;

    // stage small constants
    for (int i = t; i < 4096; i += 256) S.A4s[i] = g_A4[i];
    S.ww2[t]  = ww2[t];      // 256 == blockDim
    S.bp2s[t] = bp2[t];
    if (t < G) { S.sw[t] = g_sw[t]; S.cw[t] = g_cw[t]; S.bw2s[t] = bw2[t]; }

    // phase 1a: gather idx / mask / pos
    if (t < P * 16) {
        int p = t >> 4, n = n0 + p;
        int id  = knn[n * KNN + (t & 15)];
        int ip1 = id + 1;
        float m = (float)((ip1 > 0) - (ip1 < 0));
        int sid = (id > 0) ? id : 0;
        S.idx[t]  = sid;
        S.mask[t] = m;
        #pragma unroll
        for (int d = 0; d < 3; d++)
            S.pos[t * 4 + d] = (coord[sid * 3 + d] - coord[n * 3 + d]) * m;
    }
    __syncthreads();

    // phase 1b: lb = mask*kW[idx] - qW[n]
    for (int o = t; o < P * 16 * G; o += 256) {
        int p = o >> 8, ps = o >> 4, g = o & 15;
        S.buf1[o] = S.mask[ps] * g_kW[S.idx[ps] * G + g] - g_qW[(n0 + p) * G + g];
    }

    // phase 2: hidden = relu(bn(pos @ Wp1 + bp1)); thread t = channel c
    {
        int c = t;
        float w0 = wp1[c], w1 = wp1[C + c], w2 = wp1[2 * C + c];
        float sc = g_sp[c], sh = g_tp[c];
        #pragma unroll 4
        for (int ps = 0; ps < P * 16; ps++) {
            float px = S.pos[ps * 4 + 0];
            float py = S.pos[ps * 4 + 1];
            float pz = S.pos[ps * 4 + 2];
            float h  = fmaf(px, w0, fmaf(py, w1, pz * w2));
            S.hid[ps * CP + c] = fmaxf(fmaf(h, sc, sh), 0.f);
        }
    }
    __syncthreads();

    // phase 3: u = relu(sw*(hidden@A + lb) + cw); 2x2 register tile
    {
        int pq = t >> 3, gq = t & 7;
        int ps0 = pq * 2, g0 = gq * 2;
        float a00 = 0.f, a01 = 0.f, a10 = 0.f, a11 = 0.f;
        const float4* hp0 = (const float4*)&S.hid[ps0 * CP];
        const float4* hp1 = (const float4*)&S.hid[(ps0 + 1) * CP];
        const float4* a4  = (const float4*)S.A4s;
        #pragma unroll 8
        for (int kb = 0; kb < 64; kb++) {
            float4 h0 = hp0[kb], h1 = hp1[kb];
            float4 b0 = a4[kb * 16 + g0], b1 = a4[kb * 16 + g0 + 1];
            a00 = fmaf(h0.x, b0.x, a00); a01 = fmaf(h0.x, b1.x, a01);
            a10 = fmaf(h1.x, b0.x, a10); a11 = fmaf(h1.x, b1.x, a11);
            a00 = fmaf(h0.y, b0.y, a00); a01 = fmaf(h0.y, b1.y, a01);
            a10 = fmaf(h1.y, b0.y, a10); a11 = fmaf(h1.y, b1.y, a11);
            a00 = fmaf(h0.z, b0.z, a00); a01 = fmaf(h0.z, b1.z, a01);
            a10 = fmaf(h1.z, b0.z, a10); a11 = fmaf(h1.z, b1.z, a11);
            a00 = fmaf(h0.w, b0.w, a00); a01 = fmaf(h0.w, b1.w, a01);
            a10 = fmaf(h1.w, b0.w, a10); a11 = fmaf(h1.w, b1.w, a11);
        }
        float sw0 = S.sw[g0], cw0 = S.cw[g0], sw1 = S.sw[g0 + 1], cw1 = S.cw[g0 + 1];
        int o00 = ps0 * 16 + g0;
        S.buf1[o00]          = fmaxf(fmaf(a00 + S.buf1[o00],          sw0, cw0), 0.f);
        S.buf1[o00 + 1]      = fmaxf(fmaf(a01 + S.buf1[o00 + 1],      sw1, cw1), 0.f);
        S.buf1[o00 + 16]     = fmaxf(fmaf(a10 + S.buf1[o00 + 16],     sw0, cw0), 0.f);
        S.buf1[o00 + 17]     = fmaxf(fmaf(a11 + S.buf1[o00 + 17],     sw1, cw1), 0.f);
    }
    __syncthreads();

    // phase 3b: logit2 = u @ Ww2 + bw2
    for (int o = t; o < P * 16 * G; o += 256) {
        int ps = o >> 4, g2 = o & 15;
        float acc = S.bw2s[g2];
        const float* u = &S.buf1[ps * 16];
        #pragma unroll
        for (int g = 0; g < 16; g++) acc = fmaf(u[g], S.ww2[g * 16 + g2], acc);
        S.buf2[o] = acc;
    }
    __syncthreads();

    // phase 4a: softmax over s per (p,g); apply mask
    if (t < P * G) {
        int p = t >> 4, g = t & 15;
        float mx = -1e30f;
        #pragma unroll
        for (int s = 0; s < 16; s++) mx = fmaxf(mx, S.buf2[(p * 16 + s) * 16 + g]);
        float e[16], sum = 0.f;
        #pragma unroll
        for (int s = 0; s < 16; s++) {
            e[s] = __expf(S.buf2[(p * 16 + s) * 16 + g] - mx);
            sum += e[s];
        }
        float inv = 1.f / sum, ws = 0.f;
        #pragma unroll
        for (int s = 0; s < 16; s++) {
            float w = e[s] * inv * S.mask[p * 16 + s];
            S.buf2[(p * 16 + s) * 16 + g] = w;
            ws += w;
        }
        S.wsum[t] = ws;
    }
    __syncthreads();

    // phase 4b: hw[p][g][c] = sum_s w[p][s][g]*hid[p][s][c], in place
    // each thread owns 4-channel column slice of one p -> no mid-phase barrier
    {
        int p = t >> 6, c0 = (t & 63) * 4;
        float4 acc[16];
        #pragma unroll
        for (int g = 0; g < 16; g++) acc[g] = make_float4(0.f, 0.f, 0.f, 0.f);
        const float4* wv4 = (const float4*)S.buf2;
        #pragma unroll
        for (int s = 0; s < 16; s++) {
            float4 h = *(const float4*)&S.hid[(p * 16 + s) * CP + c0];
            #pragma unroll
            for (int q = 0; q < 4; q++) {
                float4 w = wv4[(p * 16 + s) * 4 + q];
                acc[q*4+0].x = fmaf(w.x, h.x, acc[q*4+0].x); acc[q*4+0].y = fmaf(w.x, h.y, acc[q*4+0].y);
                acc[q*4+0].z = fmaf(w.x, h.z, acc[q*4+0].z); acc[q*4+0].w = fmaf(w.x, h.w, acc[q*4+0].w);
                acc[q*4+1].x = fmaf(w.y, h.x, acc[q*4+1].x); acc[q*4+1].y = fmaf(w.y, h.y, acc[q*4+1].y);
                acc[q*4+1].z = fmaf(w.y, h.z, acc[q*4+1].z); acc[q*4+1].w = fmaf(w.y, h.w, acc[q*4+1].w);
                acc[q*4+2].x = fmaf(w.z, h.x, acc[q*4+2].x); acc[q*4+2].y = fmaf(w.z, h.y, acc[q*4+2].y);
                acc[q*4+2].z = fmaf(w.z, h.z, acc[q*4+2].z); acc[q*4+2].w = fmaf(w.z, h.w, acc[q*4+2].w);
                acc[q*4+3].x = fmaf(w.w, h.x, acc[q*4+3].x); acc[q*4+3].y = fmaf(w.w, h.y, acc[q*4+3].y);
                acc[q*4+3].z = fmaf(w.w, h.z, acc[q*4+3].z); acc[q*4+3].w = fmaf(w.w, h.w, acc[q*4+3].w);
            }
        }
        #pragma unroll
        for (int g = 0; g < 16; g++)
            *(float4*)&S.hid[(p * 16 + g) * CP + c0] = acc[g];
    }
    __syncthreads();

    // phase 5: out = v-gather + hw @ Wp2 (transposed, vectorized) + bp2*wsum
    {
        int c = t, g = c >> 4;
        float b = S.bp2s[c];
        float acc0 = b * S.wsum[g],      acc1 = b * S.wsum[16 + g];
        float acc2 = b * S.wsum[32 + g], acc3 = b * S.wsum[48 + g];

        #pragma unroll
        for (int s = 0; s < 16; s++) {
            int i0 = S.idx[s], i1 = S.idx[16 + s], i2 = S.idx[32 + s], i3 = S.idx[48 + s];
            float v0 = __ldg(&g_vall[i0 * C + c]);
            float v1 = __ldg(&g_vall[i1 * C + c]);
            float v2 = __ldg(&g_vall[i2 * C + c]);
            float v3 = __ldg(&g_vall[i3 * C + c]);
            acc0 = fmaf(S.buf2[(s)      * 16 + g], v0, acc0);
            acc1 = fmaf(S.buf2[(16 + s) * 16 + g], v1, acc1);
            acc2 = fmaf(S.buf2[(32 + s) * 16 + g], v2, acc2);
            acc3 = fmaf(S.buf2[(48 + s) * 16 + g], v3, acc3);
        }

        const float4* wpt = (const float4*)&g_wp2t[c * C];
        const float4* hw0 = (const float4*)&S.hid[(g)      * CP];
        const float4* hw1 = (const float4*)&S.hid[(16 + g) * CP];
        const float4* hw2 = (const float4*)&S.hid[(32 + g) * CP];
        const float4* hw3 = (const float4*)&S.hid[(48 + g) * CP];
        #pragma unroll 4
        for (int kb = 0; kb < 64; kb++) {
            float4 wp = wpt[kb];
            float4 h0 = hw0[kb], h1 = hw1[kb], h2 = hw2[kb], h3 = hw3[kb];
            acc0 = fmaf(wp.x, h0.x, acc0); acc0 = fmaf(wp.y, h0.y, acc0);
            acc0 = fmaf(wp.z, h0.z, acc0); acc0 = fmaf(wp.w, h0.w, acc0);
            acc1 = fmaf(wp.x, h1.x, acc1); acc1 = fmaf(wp.y, h1.y, acc1);
            acc1 = fmaf(wp.z, h1.z, acc1); acc1 = fmaf(wp.w, h1.w, acc1);
            acc2 = fmaf(wp.x, h2.x, acc2); acc2 = fmaf(wp.y, h2.y, acc2);
            acc2 = fmaf(wp.z, h2.z, acc2); acc2 = fmaf(wp.w, h2.w, acc2);
            acc3 = fmaf(wp.x, h3.x, acc3); acc3 = fmaf(wp.y, h3.y, acc3);
            acc3 = fmaf(wp.z, h3.z, acc3); acc3 = fmaf(wp.w, h3.w, acc3);
        }
        out[(n0 + 0) * C + c] = acc0;
        out[(n0 + 1) * C + c] = acc1;
        out[(n0 + 2) * C + c] = acc2;
        out[(n0 + 3) * C + c] = acc3;
    }
}

// ---------------- launch ----------------------------------------------------
extern "C" void kernel_launch(void* const* d_in, const int* in_sizes, int n_in,
                              void* d_out, int out_size) {
    (void)in_sizes; (void)n_in; (void)out_size;
    const float* feat  = (const float*)d_in[0];
    const float* coord = (const float*)d_in[1];
    const int*   knn   = (const int*)  d_in[2];
    const float* Wq = (const float*)d_in[3];  const float* bq = (const float*)d_in[4];  const float* bnq = (const float*)d_in[5];
    const float* Wk = (const float*)d_in[6];  const float* bk = (const float*)d_in[7];  const float* bnk = (const float*)d_in[8];
    const float* Wv = (const float*)d_in[9];  const float* bv = (const float*)d_in[10];
    const float* Wp1 = (const float*)d_in[11]; const float* bp1 = (const float*)d_in[12]; const float* bnp = (const float*)d_in[13];
    const float* Wp2 = (const float*)d_in[14]; const float* bp2 = (const float*)d_in[15];
    const float* Ww1 = (const float*)d_in[16]; const float* bw1 = (const float*)d_in[17]; const float* bnw = (const float*)d_in[18];
    const float* Ww2 = (const float*)d_in[19]; const float* bw2 = (const float*)d_in[20];
    float* out = (float*)d_out;

    static int configured = 0;
    cudaFuncSetAttribute(k1_qkv,  cudaFuncAttributeMaxDynamicSharedMemorySize, 81920);
    cudaFuncSetAttribute(k2_attn, cudaFuncAttributeMaxDynamicSharedMemorySize, (int)sizeof(K2S));
    (void)configured;

    prep_fold<<<1, 256>>>(bq, bnq, bk, bnk, bp1, bnp, bw1, bnw, bp2, Ww1);
    prep_At<<<16, 256>>>(Wp2, Ww1);
    prep_wp2t<<<C, C>>>(Wp2);
    k1_qkv<<<NPTS / BM, 256, 81920>>>(feat, Wq, Wk, Wv, bv, Ww1);
    k2_attn<<<NPTS / P, 256, sizeof(K2S)>>>(coord, knn, Wp1, bp2, Ww2, bw2, out);
}